// round 8
// baseline (speedup 1.0000x reference)
#include <cuda_runtime.h>
#include <math.h>

// Problem constants
#define BB 128
#define TT 512
#define II 256
#define HH 512
#define GRID_SCAN 128
#define NTH 256

// ---------------------------------------------------------------------------
// Scratch (no cudaMalloc allowed): pre-activations [T][3][B][H], state, flags.
// ---------------------------------------------------------------------------
__device__ float g_pre[(size_t)TT * 3 * BB * HH];   // ~402 MB
__device__ float g_h [BB * HH];
__device__ float g_z [BB * HH];
__device__ float g_rh[BB * HH];
__device__ unsigned int g_bar  = 0;
__device__ unsigned int g_done = 0;

__device__ __forceinline__ float sigmoidf_(float v) {
    return 1.0f / (1.0f + expf(-v));
}

// CG-style grid barrier: release-arrive + acquire-spin. No __threadfence()
// (gpu-scope fence => CCTL.IVALL on sm_103a would flush our L1-resident
// weight tiles every barrier). bar.sync provides the cta-scope fence; the
// release atomic's cumulativity covers the whole CTA's prior global stores.
__device__ __forceinline__ unsigned atom_add_release(unsigned int* p, unsigned int v) {
    unsigned int old;
    asm volatile("atom.release.gpu.add.u32 %0, [%1], %2;"
                 : "=r"(old) : "l"(p), "r"(v) : "memory");
    return old;
}
__device__ __forceinline__ unsigned ld_acquire(unsigned int* p) {
    unsigned int v;
    asm volatile("ld.acquire.gpu.u32 %0, [%1];" : "=r"(v) : "l"(p) : "memory");
    return v;
}
__device__ __forceinline__ void grid_sync(unsigned int goal) {
    __syncthreads();
    if (threadIdx.x == 0) {
        atom_add_release(&g_bar, 1u);
        while (ld_acquire(&g_bar) < goal) { }
    }
    __syncthreads();
}

// ---------------------------------------------------------------------------
// Precompute kernel: pre[t][g][b][h] = dot(x[b,t,:], w_g[h,:]) + (w_bg + r_bg)
// GEMM M=B*T=65536, N=3H=1536, K=256. Tile 128x64, BK=16, 256 thr, 8x4/thread.
// ---------------------------------------------------------------------------
__global__ void __launch_bounds__(NTH)
gru_pre_kernel(const float* __restrict__ x,
               const float* __restrict__ w_z, const float* __restrict__ w_r,
               const float* __restrict__ w_h,
               const float* __restrict__ w_bz, const float* __restrict__ w_br,
               const float* __restrict__ w_bh,
               const float* __restrict__ r_bz, const float* __restrict__ r_br,
               const float* __restrict__ r_bh)
{
    __shared__ float sA[16 * 132];   // [k][m], padded
    __shared__ float sB[16 * 68];    // [k][n], padded

    const int tid  = threadIdx.x;
    const int m0   = blockIdx.y * 128;
    const int n0   = blockIdx.x * 64;
    const int gate = n0 >> 9;                 // N tiles never straddle a gate
    const int hb   = n0 & (HH - 1);

    const float* W  = (gate == 0) ? w_z  : ((gate == 1) ? w_r  : w_h);
    const float* wb = (gate == 0) ? w_bz : ((gate == 1) ? w_br : w_bh);
    const float* rb = (gate == 0) ? r_bz : ((gate == 1) ? r_br : r_bh);

    const int lr = tid & 63;            // loader row (conflict-free STS)
    const int lk = (tid >> 6) << 2;     // loader k offset {0,4,8,12}
    const int ty = tid >> 4;            // 0..15
    const int tx = tid & 15;            // 0..15

    float acc[8][4];
#pragma unroll
    for (int i = 0; i < 8; i++)
#pragma unroll
        for (int j = 0; j < 4; j++) acc[i][j] = 0.0f;

    const float* xA0 = x + (size_t)(m0 + lr)      * II + lk;
    const float* xA1 = x + (size_t)(m0 + lr + 64) * II + lk;
    const float* wB  = W + (size_t)(hb + lr)      * II + lk;

    float4 a0 = *(const float4*)(xA0);
    float4 a1 = *(const float4*)(xA1);
    float4 b0 = *(const float4*)(wB);

    for (int k0 = 0; k0 < II; k0 += 16) {
        __syncthreads();
        sA[(lk+0)*132 + lr]      = a0.x; sA[(lk+1)*132 + lr]      = a0.y;
        sA[(lk+2)*132 + lr]      = a0.z; sA[(lk+3)*132 + lr]      = a0.w;
        sA[(lk+0)*132 + lr + 64] = a1.x; sA[(lk+1)*132 + lr + 64] = a1.y;
        sA[(lk+2)*132 + lr + 64] = a1.z; sA[(lk+3)*132 + lr + 64] = a1.w;
        sB[(lk+0)*68  + lr]      = b0.x; sB[(lk+1)*68  + lr]      = b0.y;
        sB[(lk+2)*68  + lr]      = b0.z; sB[(lk+3)*68  + lr]      = b0.w;
        __syncthreads();
        if (k0 + 16 < II) {
            a0 = *(const float4*)(xA0 + k0 + 16);
            a1 = *(const float4*)(xA1 + k0 + 16);
            b0 = *(const float4*)(wB  + k0 + 16);
        }
#pragma unroll
        for (int k = 0; k < 16; k++) {
            float4 av0 = *(const float4*)(sA + k*132 + 4*ty);
            float4 av1 = *(const float4*)(sA + k*132 + 4*ty + 64);
            float4 bv  = *(const float4*)(sB + k*68  + 4*tx);
            float a[8]  = {av0.x, av0.y, av0.z, av0.w, av1.x, av1.y, av1.z, av1.w};
            float bb[4] = {bv.x, bv.y, bv.z, bv.w};
#pragma unroll
            for (int i = 0; i < 8; i++)
#pragma unroll
                for (int j = 0; j < 4; j++)
                    acc[i][j] += a[i] * bb[j];
        }
    }

    // Epilogue: add fused bias, scatter into [t][gate][b][h]
    const int hcol = hb + 4*tx;
    float bias[4];
#pragma unroll
    for (int j = 0; j < 4; j++) bias[j] = wb[hcol + j] + rb[hcol + j];

#pragma unroll
    for (int i = 0; i < 8; i++) {
        int row = (i < 4) ? (4*ty + i) : (64 + 4*ty + (i - 4));
        int m = m0 + row;
        int b = m >> 9;           // m = b*T + t, T=512
        int t = m & (TT - 1);
        size_t base = ((size_t)((t*3 + gate) * BB + b)) * HH + hcol;
        float4 v = make_float4(acc[i][0] + bias[0], acc[i][1] + bias[1],
                               acc[i][2] + bias[2], acc[i][3] + bias[3]);
        *(float4*)(g_pre + base) = v;
    }
}

// ---------------------------------------------------------------------------
// Persistent scan kernel: 128 co-resident CTAs, 512 time steps,
// 2 grid barriers per step.
//  Phase 1: ZR[128,1024] = h @ [Rz|Rr]^T ; tiles 32x32, static map -> R tile
//           (64 KB) stays L1-resident across all steps.
//  Phase 2: HH[128,512]  = (r*h) @ Rh^T ; tiles 32x16 (Rh tile 32 KB in L1),
//           fused sigmoid/tanh/update epilogues; h[b,j] carried in registers.
// ---------------------------------------------------------------------------
__global__ void __launch_bounds__(NTH)
gru_scan_kernel(const float* __restrict__ h0,
                const float* __restrict__ r_z, const float* __restrict__ r_r,
                const float* __restrict__ r_h,
                float* __restrict__ out, int write_hlast)
{
    __shared__ float sA[32 * 34];
    __shared__ float sB[32 * 34];

    const int tid = threadIdx.x;
    const int bid = blockIdx.x;
    const int ty  = tid >> 4;          // 0..15
    const int tx  = tid & 15;          // 0..15
    const int mt  = bid >> 5;          // 0..3   batch tile
    const int nt  = bid & 31;          // 0..31  column tile
    const int b0t   = mt * 32;
    const int p1_j0 = nt * 32;         // phase1 col in [0,1024)
    const int p2_j0 = nt * 16;         // phase2 col in [0,512)
    const int lr = tid >> 3;           // loader row 0..31
    const int lk = (tid & 7) << 2;     // loader k {0,4,...,28}

    // init h state (g_h for cross-CTA reads, registers for own (b,j))
    {
        int base = bid * 512 + tid * 2;
        g_h[base]     = h0[base];
        g_h[base + 1] = h0[base + 1];
    }
    const int prow0 = b0t + 2*ty;
    float hreg0 = h0[(size_t)prow0       * HH + p2_j0 + tx];
    float hreg1 = h0[(size_t)(prow0 + 1) * HH + p2_j0 + tx];

    unsigned int nbar = 0;
    grid_sync(++nbar * GRID_SCAN);

    const int   gate = (nt < 16) ? 0 : 1;
    const int   jj0  = p1_j0 - (gate << 9);
    const float* Rzr = gate ? r_r : r_z;
    const float* RB  = Rzr + (size_t)(jj0 + lr) * HH + lk;   // same tile every step -> L1

    for (int t = 0; t < TT; t++) {
        // ------------------ phase 1: z / r gates ------------------
        {
            float acc00 = 0.f, acc01 = 0.f, acc10 = 0.f, acc11 = 0.f;
            const float* Ap = g_h + (size_t)(b0t + lr) * HH + lk;
            float4 av = __ldcg((const float4*)Ap);   // cross-CTA data: L2 path
            float4 bv = __ldg ((const float4*)RB);   // read-only weights: L1
            for (int k0 = 0; k0 < HH; k0 += 32) {
                __syncthreads();
                sA[(lk+0)*34 + lr] = av.x; sA[(lk+1)*34 + lr] = av.y;
                sA[(lk+2)*34 + lr] = av.z; sA[(lk+3)*34 + lr] = av.w;
                sB[(lk+0)*34 + lr] = bv.x; sB[(lk+1)*34 + lr] = bv.y;
                sB[(lk+2)*34 + lr] = bv.z; sB[(lk+3)*34 + lr] = bv.w;
                __syncthreads();
                if (k0 + 32 < HH) {
                    av = __ldcg((const float4*)(Ap + k0 + 32));
                    bv = __ldg ((const float4*)(RB + k0 + 32));
                }
#pragma unroll
                for (int k = 0; k < 32; k++) {
                    float2 a = *(const float2*)(sA + k*34 + 2*ty);
                    float2 b = *(const float2*)(sB + k*34 + 2*tx);
                    acc00 += a.x * b.x; acc01 += a.x * b.y;
                    acc10 += a.y * b.x; acc11 += a.y * b.y;
                }
            }
            const float* pre = g_pre + ((size_t)(t*3 + gate) * BB) * HH;
            const int r0 = b0t + 2*ty;
            const int c0 = jj0 + 2*tx;
            if (gate == 0) {
                g_z[r0*HH + c0]         = sigmoidf_(acc00 + pre[r0*HH + c0]);
                g_z[r0*HH + c0 + 1]     = sigmoidf_(acc01 + pre[r0*HH + c0 + 1]);
                g_z[(r0+1)*HH + c0]     = sigmoidf_(acc10 + pre[(r0+1)*HH + c0]);
                g_z[(r0+1)*HH + c0 + 1] = sigmoidf_(acc11 + pre[(r0+1)*HH + c0 + 1]);
            } else {
                float rr00 = sigmoidf_(acc00 + pre[r0*HH + c0]);
                float rr01 = sigmoidf_(acc01 + pre[r0*HH + c0 + 1]);
                float rr10 = sigmoidf_(acc10 + pre[(r0+1)*HH + c0]);
                float rr11 = sigmoidf_(acc11 + pre[(r0+1)*HH + c0 + 1]);
                g_rh[r0*HH + c0]         = rr00 * __ldcg(g_h + r0*HH + c0);
                g_rh[r0*HH + c0 + 1]     = rr01 * __ldcg(g_h + r0*HH + c0 + 1);
                g_rh[(r0+1)*HH + c0]     = rr10 * __ldcg(g_h + (r0+1)*HH + c0);
                g_rh[(r0+1)*HH + c0 + 1] = rr11 * __ldcg(g_h + (r0+1)*HH + c0 + 1);
            }
        }
        grid_sync(++nbar * GRID_SCAN);

        // ------------------ phase 2: candidate + update ------------------
        {
            float acc0 = 0.f, acc1 = 0.f;
            const float* Ap = g_rh + (size_t)(b0t + lr) * HH + lk;
            const int brow = tid >> 4;          // 0..15
            const int bkc  = (tid & 15) << 1;   // 0..30
            const float* RhB = r_h + (size_t)(p2_j0 + brow) * HH + bkc;
            float4 av = __ldcg((const float4*)Ap);
            float2 bv = __ldg ((const float2*)RhB);
            for (int k0 = 0; k0 < HH; k0 += 32) {
                __syncthreads();
                sA[(lk+0)*34 + lr] = av.x; sA[(lk+1)*34 + lr] = av.y;
                sA[(lk+2)*34 + lr] = av.z; sA[(lk+3)*34 + lr] = av.w;
                sB[(bkc+0)*17 + brow] = bv.x;
                sB[(bkc+1)*17 + brow] = bv.y;
                __syncthreads();
                if (k0 + 32 < HH) {
                    av = __ldcg((const float4*)(Ap + k0 + 32));
                    bv = __ldg ((const float2*)(RhB + k0 + 32));
                }
#pragma unroll
                for (int k = 0; k < 32; k++) {
                    float2 a = *(const float2*)(sA + k*34 + 2*ty);
                    float  b = sB[k*17 + tx];
                    acc0 += a.x * b;
                    acc1 += a.y * b;
                }
            }
            const float* pre = g_pre + ((size_t)(t*3 + 2) * BB) * HH;
            const int r0 = b0t + 2*ty;
            const int j  = p2_j0 + tx;
            float z0  = __ldcg(g_z + r0*HH + j);
            float z1  = __ldcg(g_z + (r0+1)*HH + j);
            float hh0 = tanhf(acc0 + pre[r0*HH + j]);
            float hh1 = tanhf(acc1 + pre[(r0+1)*HH + j]);
            float hn0 = (1.0f - z0) * hh0 + z0 * hreg0;
            float hn1 = (1.0f - z1) * hh1 + z1 * hreg1;
            hreg0 = hn0; hreg1 = hn1;
            g_h[r0*HH + j]     = hn0;
            g_h[(r0+1)*HH + j] = hn1;
            out[((size_t)r0     * TT + t) * HH + j] = hn0;
            out[((size_t)(r0+1) * TT + t) * HH + j] = hn1;
            if (write_hlast && t == TT - 1) {
                out[(size_t)BB*TT*HH + (size_t)r0*HH + j]     = hn0;
                out[(size_t)BB*TT*HH + (size_t)(r0+1)*HH + j] = hn1;
            }
        }
        grid_sync(++nbar * GRID_SCAN);
    }

    // Reset barrier state for the next graph replay. Only the LAST block to
    // arrive resets; at that point every block has passed the final barrier,
    // so no one can observe the counter mid-spin.
    __syncthreads();
    if (tid == 0) {
        unsigned int old = atom_add_release(&g_done, 1u);
        if (old == GRID_SCAN - 1) {
            g_bar  = 0;
            g_done = 0;
            __threadfence();
        }
    }
}

// ---------------------------------------------------------------------------
extern "C" void kernel_launch(void* const* d_in, const int* in_sizes, int n_in,
                              void* d_out, int out_size)
{
    const float* x    = (const float*)d_in[0];
    const float* h0   = (const float*)d_in[1];
    const float* w_z  = (const float*)d_in[2];
    const float* w_r  = (const float*)d_in[3];
    const float* w_h  = (const float*)d_in[4];
    const float* r_z  = (const float*)d_in[5];
    const float* r_r  = (const float*)d_in[6];
    const float* r_h  = (const float*)d_in[7];
    const float* w_bz = (const float*)d_in[8];
    const float* w_br = (const float*)d_in[9];
    const float* w_bh = (const float*)d_in[10];
    const float* r_bz = (const float*)d_in[11];
    const float* r_br = (const float*)d_in[12];
    const float* r_bh = (const float*)d_in[13];
    float* out = (float*)d_out;

    (void)in_sizes; (void)n_in;

    // Stage 1: input-side projections + fused biases -> g_pre
    dim3 gpre(1536 / 64, (BB * TT) / 128);
    gru_pre_kernel<<<gpre, NTH>>>(x, w_z, w_r, w_h,
                                  w_bz, w_br, w_bh, r_bz, r_br, r_bh);

    // Stage 2: persistent cooperative scan over T
    int write_hlast = (out_size >= (int)(BB * TT * HH + BB * HH)) ? 1 : 0;
    gru_scan_kernel<<<GRID_SCAN, NTH>>>(h0, r_z, r_r, r_h, out, write_hlast);
}

// round 9
// speedup vs baseline: 1.0733x; 1.0733x over previous
#include <cuda_runtime.h>
#include <math.h>

// Problem constants
#define BB 128
#define TT 512
#define II 256
#define HH 512
#define GRID_SCAN 128
#define NTH 256

// ---------------------------------------------------------------------------
// Scratch (no cudaMalloc allowed): pre-activations [T][3][B][H], state, flags.
// ---------------------------------------------------------------------------
__device__ float g_pre[(size_t)TT * 3 * BB * HH];   // ~402 MB
__device__ float g_h [BB * HH];
__device__ float g_z [BB * HH];
__device__ float g_rh[BB * HH];
__device__ unsigned int g_bar  = 0;
__device__ unsigned int g_done = 0;

__device__ __forceinline__ float sigmoidf_(float v) {
    return 1.0f / (1.0f + expf(-v));
}

// CG-style grid barrier: release-arrive + acquire-spin. No __threadfence()
// (gpu-scope fence => CCTL.IVALL on sm_103a would flush our L1-resident
// weight tiles every barrier). bar.sync provides the cta-scope fence; the
// release atomic's cumulativity covers the whole CTA's prior global stores.
__device__ __forceinline__ unsigned atom_add_release(unsigned int* p, unsigned int v) {
    unsigned int old;
    asm volatile("atom.release.gpu.add.u32 %0, [%1], %2;"
                 : "=r"(old) : "l"(p), "r"(v) : "memory");
    return old;
}
__device__ __forceinline__ unsigned ld_acquire(unsigned int* p) {
    unsigned int v;
    asm volatile("ld.acquire.gpu.u32 %0, [%1];" : "=r"(v) : "l"(p) : "memory");
    return v;
}
__device__ __forceinline__ void grid_sync(unsigned int goal) {
    __syncthreads();
    if (threadIdx.x == 0) {
        atom_add_release(&g_bar, 1u);
        while (ld_acquire(&g_bar) < goal) { }
    }
    __syncthreads();
}

// ---------------------------------------------------------------------------
// Precompute kernel: pre[t][g][b][h] = dot(x[b,t,:], w_g[h,:]) + (w_bg + r_bg)
// GEMM M=B*T=65536, N=3H=1536, K=256. Tile 128x64, BK=16, 256 thr, 8x4/thread.
// ---------------------------------------------------------------------------
__global__ void __launch_bounds__(NTH)
gru_pre_kernel(const float* __restrict__ x,
               const float* __restrict__ w_z, const float* __restrict__ w_r,
               const float* __restrict__ w_h,
               const float* __restrict__ w_bz, const float* __restrict__ w_br,
               const float* __restrict__ w_bh,
               const float* __restrict__ r_bz, const float* __restrict__ r_br,
               const float* __restrict__ r_bh)
{
    __shared__ float sA[16 * 132];   // [k][m], padded
    __shared__ float sB[16 * 68];    // [k][n], padded

    const int tid  = threadIdx.x;
    const int m0   = blockIdx.y * 128;
    const int n0   = blockIdx.x * 64;
    const int gate = n0 >> 9;                 // N tiles never straddle a gate
    const int hb   = n0 & (HH - 1);

    const float* W  = (gate == 0) ? w_z  : ((gate == 1) ? w_r  : w_h);
    const float* wb = (gate == 0) ? w_bz : ((gate == 1) ? w_br : w_bh);
    const float* rb = (gate == 0) ? r_bz : ((gate == 1) ? r_br : r_bh);

    const int lr = tid & 63;            // loader row (conflict-free STS)
    const int lk = (tid >> 6) << 2;     // loader k offset {0,4,8,12}
    const int ty = tid >> 4;            // 0..15
    const int tx = tid & 15;            // 0..15

    float acc[8][4];
#pragma unroll
    for (int i = 0; i < 8; i++)
#pragma unroll
        for (int j = 0; j < 4; j++) acc[i][j] = 0.0f;

    const float* xA0 = x + (size_t)(m0 + lr)      * II + lk;
    const float* xA1 = x + (size_t)(m0 + lr + 64) * II + lk;
    const float* wB  = W + (size_t)(hb + lr)      * II + lk;

    float4 a0 = *(const float4*)(xA0);
    float4 a1 = *(const float4*)(xA1);
    float4 b0 = *(const float4*)(wB);

    for (int k0 = 0; k0 < II; k0 += 16) {
        __syncthreads();
        sA[(lk+0)*132 + lr]      = a0.x; sA[(lk+1)*132 + lr]      = a0.y;
        sA[(lk+2)*132 + lr]      = a0.z; sA[(lk+3)*132 + lr]      = a0.w;
        sA[(lk+0)*132 + lr + 64] = a1.x; sA[(lk+1)*132 + lr + 64] = a1.y;
        sA[(lk+2)*132 + lr + 64] = a1.z; sA[(lk+3)*132 + lr + 64] = a1.w;
        sB[(lk+0)*68  + lr]      = b0.x; sB[(lk+1)*68  + lr]      = b0.y;
        sB[(lk+2)*68  + lr]      = b0.z; sB[(lk+3)*68  + lr]      = b0.w;
        __syncthreads();
        if (k0 + 16 < II) {
            a0 = *(const float4*)(xA0 + k0 + 16);
            a1 = *(const float4*)(xA1 + k0 + 16);
            b0 = *(const float4*)(wB  + k0 + 16);
        }
#pragma unroll
        for (int k = 0; k < 16; k++) {
            float4 av0 = *(const float4*)(sA + k*132 + 4*ty);
            float4 av1 = *(const float4*)(sA + k*132 + 4*ty + 64);
            float4 bv  = *(const float4*)(sB + k*68  + 4*tx);
            float a[8]  = {av0.x, av0.y, av0.z, av0.w, av1.x, av1.y, av1.z, av1.w};
            float bb[4] = {bv.x, bv.y, bv.z, bv.w};
#pragma unroll
            for (int i = 0; i < 8; i++)
#pragma unroll
                for (int j = 0; j < 4; j++)
                    acc[i][j] += a[i] * bb[j];
        }
    }

    // Epilogue: add fused bias, scatter into [t][gate][b][h]
    const int hcol = hb + 4*tx;
    float bias[4];
#pragma unroll
    for (int j = 0; j < 4; j++) bias[j] = wb[hcol + j] + rb[hcol + j];

#pragma unroll
    for (int i = 0; i < 8; i++) {
        int row = (i < 4) ? (4*ty + i) : (64 + 4*ty + (i - 4));
        int m = m0 + row;
        int b = m >> 9;           // m = b*T + t, T=512
        int t = m & (TT - 1);
        size_t base = ((size_t)((t*3 + gate) * BB + b)) * HH + hcol;
        float4 v = make_float4(acc[i][0] + bias[0], acc[i][1] + bias[1],
                               acc[i][2] + bias[2], acc[i][3] + bias[3]);
        *(float4*)(g_pre + base) = v;
    }
}

// ---------------------------------------------------------------------------
// Persistent scan kernel: 128 co-resident CTAs, 512 time steps,
// 2 grid barriers per step.
//  Phase 1: ZR[128,1024] = h @ [Rz|Rr]^T ; tiles 32x32, static map -> R tile
//           (64 KB) stays L1-resident across all steps.
//  Phase 2: HH[128,512]  = (r*h) @ Rh^T ; tiles 32x16 (Rh tile 32 KB in L1),
//           fused sigmoid/tanh/update epilogues; h[b,j] carried in registers.
// ---------------------------------------------------------------------------
__global__ void __launch_bounds__(NTH)
gru_scan_kernel(const float* __restrict__ h0,
                const float* __restrict__ r_z, const float* __restrict__ r_r,
                const float* __restrict__ r_h,
                float* __restrict__ out, int write_hlast)
{
    __shared__ float sA[32 * 34];
    __shared__ float sB[32 * 34];

    const int tid = threadIdx.x;
    const int bid = blockIdx.x;
    const int ty  = tid >> 4;          // 0..15
    const int tx  = tid & 15;          // 0..15
    const int mt  = bid >> 5;          // 0..3   batch tile
    const int nt  = bid & 31;          // 0..31  column tile
    const int b0t   = mt * 32;
    const int p1_j0 = nt * 32;         // phase1 col in [0,1024)
    const int p2_j0 = nt * 16;         // phase2 col in [0,512)
    const int lr = tid >> 3;           // loader row 0..31
    const int lk = (tid & 7) << 2;     // loader k {0,4,...,28}

    // init h state (g_h for cross-CTA reads, registers for own (b,j))
    {
        int base = bid * 512 + tid * 2;
        g_h[base]     = h0[base];
        g_h[base + 1] = h0[base + 1];
    }
    const int prow0 = b0t + 2*ty;
    float hreg0 = h0[(size_t)prow0       * HH + p2_j0 + tx];
    float hreg1 = h0[(size_t)(prow0 + 1) * HH + p2_j0 + tx];

    unsigned int nbar = 0;
    grid_sync(++nbar * GRID_SCAN);

    const int   gate = (nt < 16) ? 0 : 1;
    const int   jj0  = p1_j0 - (gate << 9);
    const float* Rzr = gate ? r_r : r_z;
    const float* RB  = Rzr + (size_t)(jj0 + lr) * HH + lk;   // same tile every step -> L1

    for (int t = 0; t < TT; t++) {
        // ------------------ phase 1: z / r gates ------------------
        {
            float acc00 = 0.f, acc01 = 0.f, acc10 = 0.f, acc11 = 0.f;
            const float* Ap = g_h + (size_t)(b0t + lr) * HH + lk;
            float4 av = __ldcg((const float4*)Ap);   // cross-CTA data: L2 path
            float4 bv = __ldg ((const float4*)RB);   // read-only weights: L1
            for (int k0 = 0; k0 < HH; k0 += 32) {
                __syncthreads();
                sA[(lk+0)*34 + lr] = av.x; sA[(lk+1)*34 + lr] = av.y;
                sA[(lk+2)*34 + lr] = av.z; sA[(lk+3)*34 + lr] = av.w;
                sB[(lk+0)*34 + lr] = bv.x; sB[(lk+1)*34 + lr] = bv.y;
                sB[(lk+2)*34 + lr] = bv.z; sB[(lk+3)*34 + lr] = bv.w;
                __syncthreads();
                if (k0 + 32 < HH) {
                    av = __ldcg((const float4*)(Ap + k0 + 32));
                    bv = __ldg ((const float4*)(RB + k0 + 32));
                }
#pragma unroll
                for (int k = 0; k < 32; k++) {
                    float2 a = *(const float2*)(sA + k*34 + 2*ty);
                    float2 b = *(const float2*)(sB + k*34 + 2*tx);
                    acc00 += a.x * b.x; acc01 += a.x * b.y;
                    acc10 += a.y * b.x; acc11 += a.y * b.y;
                }
            }
            const float* pre = g_pre + ((size_t)(t*3 + gate) * BB) * HH;
            const int r0 = b0t + 2*ty;
            const int c0 = jj0 + 2*tx;
            if (gate == 0) {
                g_z[r0*HH + c0]         = sigmoidf_(acc00 + pre[r0*HH + c0]);
                g_z[r0*HH + c0 + 1]     = sigmoidf_(acc01 + pre[r0*HH + c0 + 1]);
                g_z[(r0+1)*HH + c0]     = sigmoidf_(acc10 + pre[(r0+1)*HH + c0]);
                g_z[(r0+1)*HH + c0 + 1] = sigmoidf_(acc11 + pre[(r0+1)*HH + c0 + 1]);
            } else {
                float rr00 = sigmoidf_(acc00 + pre[r0*HH + c0]);
                float rr01 = sigmoidf_(acc01 + pre[r0*HH + c0 + 1]);
                float rr10 = sigmoidf_(acc10 + pre[(r0+1)*HH + c0]);
                float rr11 = sigmoidf_(acc11 + pre[(r0+1)*HH + c0 + 1]);
                g_rh[r0*HH + c0]         = rr00 * __ldcg(g_h + r0*HH + c0);
                g_rh[r0*HH + c0 + 1]     = rr01 * __ldcg(g_h + r0*HH + c0 + 1);
                g_rh[(r0+1)*HH + c0]     = rr10 * __ldcg(g_h + (r0+1)*HH + c0);
                g_rh[(r0+1)*HH + c0 + 1] = rr11 * __ldcg(g_h + (r0+1)*HH + c0 + 1);
            }
        }
        grid_sync(++nbar * GRID_SCAN);

        // ------------------ phase 2: candidate + update ------------------
        {
            float acc0 = 0.f, acc1 = 0.f;
            const float* Ap = g_rh + (size_t)(b0t + lr) * HH + lk;
            const int brow = tid >> 4;          // 0..15
            const int bkc  = (tid & 15) << 1;   // 0..30
            const float* RhB = r_h + (size_t)(p2_j0 + brow) * HH + bkc;
            float4 av = __ldcg((const float4*)Ap);
            float2 bv = __ldg ((const float2*)RhB);
            for (int k0 = 0; k0 < HH; k0 += 32) {
                __syncthreads();
                sA[(lk+0)*34 + lr] = av.x; sA[(lk+1)*34 + lr] = av.y;
                sA[(lk+2)*34 + lr] = av.z; sA[(lk+3)*34 + lr] = av.w;
                sB[(bkc+0)*17 + brow] = bv.x;
                sB[(bkc+1)*17 + brow] = bv.y;
                __syncthreads();
                if (k0 + 32 < HH) {
                    av = __ldcg((const float4*)(Ap + k0 + 32));
                    bv = __ldg ((const float2*)(RhB + k0 + 32));
                }
#pragma unroll
                for (int k = 0; k < 32; k++) {
                    float2 a = *(const float2*)(sA + k*34 + 2*ty);
                    float  b = sB[k*17 + tx];
                    acc0 += a.x * b;
                    acc1 += a.y * b;
                }
            }
            const float* pre = g_pre + ((size_t)(t*3 + 2) * BB) * HH;
            const int r0 = b0t + 2*ty;
            const int j  = p2_j0 + tx;
            float z0  = __ldcg(g_z + r0*HH + j);
            float z1  = __ldcg(g_z + (r0+1)*HH + j);
            float hh0 = tanhf(acc0 + pre[r0*HH + j]);
            float hh1 = tanhf(acc1 + pre[(r0+1)*HH + j]);
            float hn0 = (1.0f - z0) * hh0 + z0 * hreg0;
            float hn1 = (1.0f - z1) * hh1 + z1 * hreg1;
            hreg0 = hn0; hreg1 = hn1;
            g_h[r0*HH + j]     = hn0;
            g_h[(r0+1)*HH + j] = hn1;
            out[((size_t)r0     * TT + t) * HH + j] = hn0;
            out[((size_t)(r0+1) * TT + t) * HH + j] = hn1;
            if (write_hlast && t == TT - 1) {
                out[(size_t)BB*TT*HH + (size_t)r0*HH + j]     = hn0;
                out[(size_t)BB*TT*HH + (size_t)(r0+1)*HH + j] = hn1;
            }
        }
        grid_sync(++nbar * GRID_SCAN);
    }

    // Reset barrier state for the next graph replay. Only the LAST block to
    // arrive resets; at that point every block has passed the final barrier,
    // so no one can observe the counter mid-spin.
    __syncthreads();
    if (tid == 0) {
        unsigned int old = atom_add_release(&g_done, 1u);
        if (old == GRID_SCAN - 1) {
            g_bar  = 0;
            g_done = 0;
            __threadfence();
        }
    }
}

// ---------------------------------------------------------------------------
extern "C" void kernel_launch(void* const* d_in, const int* in_sizes, int n_in,
                              void* d_out, int out_size)
{
    const float* x    = (const float*)d_in[0];
    const float* h0   = (const float*)d_in[1];
    const float* w_z  = (const float*)d_in[2];
    const float* w_r  = (const float*)d_in[3];
    const float* w_h  = (const float*)d_in[4];
    const float* r_z  = (const float*)d_in[5];
    const float* r_r  = (const float*)d_in[6];
    const float* r_h  = (const float*)d_in[7];
    const float* w_bz = (const float*)d_in[8];
    const float* w_br = (const float*)d_in[9];
    const float* w_bh = (const float*)d_in[10];
    const float* r_bz = (const float*)d_in[11];
    const float* r_br = (const float*)d_in[12];
    const float* r_bh = (const float*)d_in[13];
    float* out = (float*)d_out;

    (void)in_sizes; (void)n_in;

    // Stage 1: input-side projections + fused biases -> g_pre
    dim3 gpre(1536 / 64, (BB * TT) / 128);
    gru_pre_kernel<<<gpre, NTH>>>(x, w_z, w_r, w_h,
                                  w_bz, w_br, w_bh, r_bz, r_br, r_bh);

    // Stage 2: persistent cooperative scan over T
    int write_hlast = (out_size >= (int)(BB * TT * HH + BB * HH)) ? 1 : 0;
    gru_scan_kernel<<<GRID_SCAN, NTH>>>(h0, r_z, r_r, r_h, out, write_hlast);
}

// round 10
// speedup vs baseline: 1.4100x; 1.3138x over previous
#include <cuda_runtime.h>
#include <math.h>

#define BB 128
#define TT 512
#define II 256
#define HH 512
#define NTH 256
#define PK 516            // sH row pitch (floats), 16B-aligned, bank-staggered

typedef unsigned long long ull;

// ---------------------------------------------------------------------------
// Scratch (no cudaMalloc allowed)
// ---------------------------------------------------------------------------
__device__ float g_pre[(size_t)TT * 3 * BB * HH];   // [t][gate][b][h]
__device__ float g_h [BB * HH];
__device__ float g_z [BB * HH];
__device__ float g_rh[BB * HH];
__device__ unsigned int g_bars[4 * 32];             // 4 group counters, 128B apart
__device__ unsigned int g_done = 0;

// Packed fp32x2 FMA (SASS FFMA2) — only reachable via PTX.
__device__ __forceinline__ void ffma2(ull& d, ull a, ull b) {
    asm("fma.rn.f32x2 %0, %1, %2, %0;" : "+l"(d) : "l"(a), "l"(b));
}
__device__ __forceinline__ float pair_sum(ull v) {
    return __uint_as_float((unsigned)v) + __uint_as_float((unsigned)(v >> 32));
}
__device__ __forceinline__ float fsig(float v) {
    return 1.0f / (1.0f + __expf(-v));
}

// Release/acquire grid barrier (no gpu-scope fence in hot path: CCTL.IVALL
// would flush L1). bar.sync + release-atomic cumulativity order the CTA's
// prior global stores.
__device__ __forceinline__ unsigned atom_add_release(unsigned int* p, unsigned int v) {
    unsigned int old;
    asm volatile("atom.release.gpu.add.u32 %0, [%1], %2;"
                 : "=r"(old) : "l"(p), "r"(v) : "memory");
    return old;
}
__device__ __forceinline__ unsigned ld_acquire(unsigned int* p) {
    unsigned int v;
    asm volatile("ld.acquire.gpu.u32 %0, [%1];" : "=r"(v) : "l"(p) : "memory");
    return v;
}
__device__ __forceinline__ void group_sync(unsigned int* bar, unsigned int goal) {
    __syncthreads();
    if (threadIdx.x == 0) {
        atom_add_release(bar, 1u);
        while (ld_acquire(bar) < goal) { }
    }
    __syncthreads();
}

// ---------------------------------------------------------------------------
// Precompute kernel (unchanged from R7 — known good):
// pre[t][g][b][h] = dot(x[b,t,:], w_g[h,:]) + (w_bg + r_bg)
// ---------------------------------------------------------------------------
__global__ void __launch_bounds__(NTH)
gru_pre_kernel(const float* __restrict__ x,
               const float* __restrict__ w_z, const float* __restrict__ w_r,
               const float* __restrict__ w_h,
               const float* __restrict__ w_bz, const float* __restrict__ w_br,
               const float* __restrict__ w_bh,
               const float* __restrict__ r_bz, const float* __restrict__ r_br,
               const float* __restrict__ r_bh)
{
    __shared__ float sA[16 * 132];
    __shared__ float sB[16 * 68];

    const int tid  = threadIdx.x;
    const int m0   = blockIdx.y * 128;
    const int n0   = blockIdx.x * 64;
    const int gate = n0 >> 9;
    const int hb   = n0 & (HH - 1);

    const float* W  = (gate == 0) ? w_z  : ((gate == 1) ? w_r  : w_h);
    const float* wb = (gate == 0) ? w_bz : ((gate == 1) ? w_br : w_bh);
    const float* rb = (gate == 0) ? r_bz : ((gate == 1) ? r_br : r_bh);

    const int lr = tid & 63;
    const int lk = (tid >> 6) << 2;
    const int ty = tid >> 4;
    const int tx = tid & 15;

    float acc[8][4];
#pragma unroll
    for (int i = 0; i < 8; i++)
#pragma unroll
        for (int j = 0; j < 4; j++) acc[i][j] = 0.0f;

    const float* xA0 = x + (size_t)(m0 + lr)      * II + lk;
    const float* xA1 = x + (size_t)(m0 + lr + 64) * II + lk;
    const float* wB  = W + (size_t)(hb + lr)      * II + lk;

    float4 a0 = *(const float4*)(xA0);
    float4 a1 = *(const float4*)(xA1);
    float4 b0 = *(const float4*)(wB);

    for (int k0 = 0; k0 < II; k0 += 16) {
        __syncthreads();
        sA[(lk+0)*132 + lr]      = a0.x; sA[(lk+1)*132 + lr]      = a0.y;
        sA[(lk+2)*132 + lr]      = a0.z; sA[(lk+3)*132 + lr]      = a0.w;
        sA[(lk+0)*132 + lr + 64] = a1.x; sA[(lk+1)*132 + lr + 64] = a1.y;
        sA[(lk+2)*132 + lr + 64] = a1.z; sA[(lk+3)*132 + lr + 64] = a1.w;
        sB[(lk+0)*68  + lr]      = b0.x; sB[(lk+1)*68  + lr]      = b0.y;
        sB[(lk+2)*68  + lr]      = b0.z; sB[(lk+3)*68  + lr]      = b0.w;
        __syncthreads();
        if (k0 + 16 < II) {
            a0 = *(const float4*)(xA0 + k0 + 16);
            a1 = *(const float4*)(xA1 + k0 + 16);
            b0 = *(const float4*)(wB  + k0 + 16);
        }
#pragma unroll
        for (int k = 0; k < 16; k++) {
            float4 av0 = *(const float4*)(sA + k*132 + 4*ty);
            float4 av1 = *(const float4*)(sA + k*132 + 4*ty + 64);
            float4 bv  = *(const float4*)(sB + k*68  + 4*tx);
            float a[8]  = {av0.x, av0.y, av0.z, av0.w, av1.x, av1.y, av1.z, av1.w};
            float bb[4] = {bv.x, bv.y, bv.z, bv.w};
#pragma unroll
            for (int i = 0; i < 8; i++)
#pragma unroll
                for (int j = 0; j < 4; j++)
                    acc[i][j] += a[i] * bb[j];
        }
    }

    const int hcol = hb + 4*tx;
    float bias[4];
#pragma unroll
    for (int j = 0; j < 4; j++) bias[j] = wb[hcol + j] + rb[hcol + j];

#pragma unroll
    for (int i = 0; i < 8; i++) {
        int row = (i < 4) ? (4*ty + i) : (64 + 4*ty + (i - 4));
        int m = m0 + row;
        int b = m >> 9;
        int t = m & (TT - 1);
        size_t base = ((size_t)((t*3 + gate) * BB + b)) * HH + hcol;
        *(float4*)(g_pre + base) = make_float4(acc[i][0] + bias[0], acc[i][1] + bias[1],
                                               acc[i][2] + bias[2], acc[i][3] + bias[3]);
    }
}

// ---------------------------------------------------------------------------
// Persistent scan: 128 CTAs (4 independent batch groups of 32), 512 steps.
// smem: sW1[k2][64]=Rz/Rr tile (64KB), sW2[k2][32]=Rh tile (32KB),
//       sH[32][PK]= staged h / rh (66KB). fp32x2 inner loops.
// ---------------------------------------------------------------------------
#define SMEM_W1 0
#define SMEM_W2 16384
#define SMEM_SH 24576
#define SCAN_SMEM_BYTES ((24576 + 32 * PK) * 4)

__device__ __forceinline__ void stage32x512(const float* __restrict__ src,
                                            float* sH, int b0t, int tid) {
#pragma unroll
    for (int i = 0; i < 16; i++) {
        int idx = i * NTH + tid;            // 0..4095
        int row = idx >> 7, k4 = idx & 127; // coalesced LDG, conflict-free STS
        float4 v = __ldcg((const float4*)(src + (size_t)(b0t + row) * HH + 4 * k4));
        *(float4*)(sH + row * PK + 4 * k4) = v;
    }
}

__global__ void __launch_bounds__(NTH, 1)
gru_scan_kernel(const float* __restrict__ h0,
                const float* __restrict__ r_z, const float* __restrict__ r_r,
                const float* __restrict__ r_h,
                float* __restrict__ out, int write_hlast)
{
    extern __shared__ float sm[];
    float* sW1 = sm + SMEM_W1;   // [k2][j*2 + (k&1)], j 0..31, pitch 64
    float* sW2 = sm + SMEM_W2;   // [k2][j*2 + (k&1)], j 0..15, pitch 32
    float* sH  = sm + SMEM_SH;   // [row][k], pitch PK

    const int tid = threadIdx.x;
    const int bid = blockIdx.x;
    const int ty  = tid >> 4;            // 0..15
    const int tx  = tid & 15;            // 0..15
    const int mt  = bid >> 5;            // batch group 0..3
    const int nt  = bid & 31;            // column tile 0..31
    const int b0t   = mt * 32;
    const int p2_j0 = nt * 16;
    const int gate  = (nt < 16) ? 0 : 1;
    const int jj0   = (nt - (gate << 4)) * 32;   // gate-local phase1 col base

    unsigned int* bar = &g_bars[mt * 32];
    const float* Rzr = gate ? r_r : r_z;

    // Load persistent weight tiles into smem (k-pair interleaved layout)
#pragma unroll
    for (int i = 0; i < 16; i++) {
        int idx = i * NTH + tid;            // 0..4095
        int j = idx >> 7, k4 = idx & 127;
        float4 v = *(const float4*)(Rzr + (size_t)(jj0 + j) * HH + 4 * k4);
        *(float2*)(sW1 + (2*k4)   * 64 + 2*j) = make_float2(v.x, v.y);
        *(float2*)(sW1 + (2*k4+1) * 64 + 2*j) = make_float2(v.z, v.w);
    }
#pragma unroll
    for (int i = 0; i < 8; i++) {
        int idx = i * NTH + tid;            // 0..2047
        int j = idx >> 7, k4 = idx & 127;
        float4 v = *(const float4*)(r_h + (size_t)(p2_j0 + j) * HH + 4 * k4);
        *(float2*)(sW2 + (2*k4)   * 32 + 2*j) = make_float2(v.x, v.y);
        *(float2*)(sW2 + (2*k4+1) * 32 + 2*j) = make_float2(v.z, v.w);
    }

    // init h state: CTA bid owns g_h row bid; hregs for own (b, j)
    {
        int base = bid * 512 + tid * 2;
        g_h[base]     = h0[base];
        g_h[base + 1] = h0[base + 1];
    }
    const int r0 = b0t + 2 * ty;
    float hreg0 = h0[(size_t)r0       * HH + p2_j0 + tx];
    float hreg1 = h0[(size_t)(r0 + 1) * HH + p2_j0 + tx];

    unsigned int nbar = 0;
    group_sync(bar, ++nbar * 32);

    const float* hA = sH + (2 * ty)     * PK;
    const float* hB = sH + (2 * ty + 1) * PK;

    for (int t = 0; t < TT; t++) {
        // ---------------- phase 1: z / r gate GEMM (32x32 x 512k) ----------
        stage32x512(g_h, sH, b0t, tid);
        __syncthreads();
        {
            ull acc00 = 0, acc01 = 0, acc10 = 0, acc11 = 0;
#pragma unroll 8
            for (int k2 = 0; k2 < 256; k2++) {
                ull a0 = *(const ull*)(hA + 2 * k2);
                ull a1 = *(const ull*)(hB + 2 * k2);
                ulonglong2 b = *(const ulonglong2*)(sW1 + k2 * 64 + 4 * tx);
                ffma2(acc00, a0, b.x); ffma2(acc01, a0, b.y);
                ffma2(acc10, a1, b.x); ffma2(acc11, a1, b.y);
            }
            const float* pre = g_pre + (size_t)(t * 3 + gate) * BB * HH;
            const int c0 = jj0 + 2 * tx;
            float s00 = pair_sum(acc00) + pre[(size_t)r0 * HH + c0];
            float s01 = pair_sum(acc01) + pre[(size_t)r0 * HH + c0 + 1];
            float s10 = pair_sum(acc10) + pre[(size_t)(r0+1) * HH + c0];
            float s11 = pair_sum(acc11) + pre[(size_t)(r0+1) * HH + c0 + 1];
            if (gate == 0) {
                g_z[r0*HH + c0]         = fsig(s00);
                g_z[r0*HH + c0 + 1]     = fsig(s01);
                g_z[(r0+1)*HH + c0]     = fsig(s10);
                g_z[(r0+1)*HH + c0 + 1] = fsig(s11);
            } else {
                g_rh[r0*HH + c0]         = fsig(s00) * hA[c0];
                g_rh[r0*HH + c0 + 1]     = fsig(s01) * hA[c0 + 1];
                g_rh[(r0+1)*HH + c0]     = fsig(s10) * hB[c0];
                g_rh[(r0+1)*HH + c0 + 1] = fsig(s11) * hB[c0 + 1];
            }
        }
        group_sync(bar, ++nbar * 32);

        // ---------------- phase 2: candidate GEMM (32x16 x 512k) + update --
        stage32x512(g_rh, sH, b0t, tid);
        __syncthreads();
        {
            ull acc0 = 0, acc1 = 0;
#pragma unroll 8
            for (int k2 = 0; k2 < 256; k2++) {
                ull a0 = *(const ull*)(hA + 2 * k2);
                ull a1 = *(const ull*)(hB + 2 * k2);
                ull bv = *(const ull*)(sW2 + k2 * 32 + 2 * tx);
                ffma2(acc0, a0, bv);
                ffma2(acc1, a1, bv);
            }
            const float* pre = g_pre + (size_t)(t * 3 + 2) * BB * HH;
            const int j = p2_j0 + tx;
            float z0  = __ldcg(g_z + r0 * HH + j);
            float z1  = __ldcg(g_z + (r0 + 1) * HH + j);
            float hh0 = tanhf(pair_sum(acc0) + pre[(size_t)r0 * HH + j]);
            float hh1 = tanhf(pair_sum(acc1) + pre[(size_t)(r0 + 1) * HH + j]);
            float hn0 = (1.0f - z0) * hh0 + z0 * hreg0;
            float hn1 = (1.0f - z1) * hh1 + z1 * hreg1;
            hreg0 = hn0; hreg1 = hn1;
            g_h[r0 * HH + j]       = hn0;
            g_h[(r0 + 1) * HH + j] = hn1;
            out[((size_t)r0       * TT + t) * HH + j] = hn0;
            out[((size_t)(r0 + 1) * TT + t) * HH + j] = hn1;
            if (write_hlast && t == TT - 1) {
                out[(size_t)BB*TT*HH + (size_t)r0 * HH + j]       = hn0;
                out[(size_t)BB*TT*HH + (size_t)(r0 + 1) * HH + j] = hn1;
            }
        }
        group_sync(bar, ++nbar * 32);
    }

    // Reset barrier state for next graph replay; last CTA overall resets.
    __syncthreads();
    if (tid == 0) {
        unsigned int old = atom_add_release(&g_done, 1u);
        if (old == BB - 1) {
            g_bars[0] = 0; g_bars[32] = 0; g_bars[64] = 0; g_bars[96] = 0;
            g_done = 0;
            __threadfence();
        }
    }
}

// ---------------------------------------------------------------------------
extern "C" void kernel_launch(void* const* d_in, const int* in_sizes, int n_in,
                              void* d_out, int out_size)
{
    const float* x    = (const float*)d_in[0];
    const float* h0   = (const float*)d_in[1];
    const float* w_z  = (const float*)d_in[2];
    const float* w_r  = (const float*)d_in[3];
    const float* w_h  = (const float*)d_in[4];
    const float* r_z  = (const float*)d_in[5];
    const float* r_r  = (const float*)d_in[6];
    const float* r_h  = (const float*)d_in[7];
    const float* w_bz = (const float*)d_in[8];
    const float* w_br = (const float*)d_in[9];
    const float* w_bh = (const float*)d_in[10];
    const float* r_bz = (const float*)d_in[11];
    const float* r_br = (const float*)d_in[12];
    const float* r_bh = (const float*)d_in[13];
    float* out = (float*)d_out;

    (void)in_sizes; (void)n_in;

    cudaFuncSetAttribute(gru_scan_kernel,
                         cudaFuncAttributeMaxDynamicSharedMemorySize,
                         SCAN_SMEM_BYTES);

    dim3 gpre(1536 / 64, (BB * TT) / 128);
    gru_pre_kernel<<<gpre, NTH>>>(x, w_z, w_r, w_h,
                                  w_bz, w_br, w_bh, r_bz, r_br, r_bh);

    int write_hlast = (out_size >= (int)(BB * TT * HH + BB * HH)) ? 1 : 0;
    gru_scan_kernel<<<BB, NTH, SCAN_SMEM_BYTES>>>(h0, r_z, r_r, r_h, out, write_hlast);
}